// round 14
// baseline (speedup 1.0000x reference)
#include <cuda_runtime.h>
#include <cstdint>
#include <cmath>

#define BB   256
#define TT   1024
#define OBS  64
#define NN   512
#define AA   8
#define BETA 0.9f
#define V_TH 1.0f

#define BT      16                 // batch rows per block (= warps per block)
#define NT      64                 // neurons per block
#define NBG     (BB / BT)          // 16 batch groups
#define NNT     (NN / NT)          // 8 neuron tiles per group
#define GRID    (NBG * NNT)        // 128 blocks, all co-resident (1/SM)
#define THREADS 512

struct __align__(128) GroupBar { unsigned count; unsigned flag; unsigned pad[30]; };

// Scratch: __device__ globals (runtime allocation is forbidden)
__device__ float    g_WT[NN * NN];               // W_T[j][i] = W_rec[i][j]
__device__ float    g_I[(size_t)BB * TT * NN];   // x @ W_in^T, precomputed
__device__ unsigned g_mask[2][BB][NN / 32];      // spike bitmasks, parity-buffered
__device__ float    g_part[2][BB][NNT][AA];      // output partials, parity-buffered
__device__ GroupBar g_bar[NBG];                  // per-group barrier lines

// ---------- fused prep + input GEMM ----------
// blockIdx.y < 8 : GEMM tile  g_I[r,i] = sum_k X[r,k]*Win[i,k]  (bitwise-load-bearing)
// blockIdx.y == 8: prep plane (W transpose, mask(0) zero, barrier reset)
__global__ void __launch_bounds__(256, 2) fused_prep_ingemm(const float* __restrict__ X,
                                                            const float* __restrict__ Win,
                                                            const float* __restrict__ Wrec)
{
    if (blockIdx.y == 8) {
        int idx = blockIdx.x * 256 + threadIdx.x;
        if (idx < NN * NN) {
            int i = idx >> 9, j = idx & (NN - 1);
            g_WT[j * NN + i] = Wrec[idx];
        }
        if (idx < BB * (NN / 32)) ((unsigned*)g_mask)[idx] = 0u;   // g_mask[0] zeroed
        if (idx < NBG) { g_bar[idx].count = 0u; g_bar[idx].flag = 0u; }
        return;
    }

    __shared__ float As[128][OBS];
    __shared__ float Bs[OBS][64];
    const int row0 = blockIdx.x * 128;
    const int col0 = blockIdx.y * 64;
    const int tid  = threadIdx.x;

    #pragma unroll
    for (int l = tid; l < 128 * 16; l += 256) {
        int r = l >> 4, kq = l & 15;
        float4 v = reinterpret_cast<const float4*>(X + (size_t)(row0 + r) * OBS)[kq];
        *reinterpret_cast<float4*>(&As[r][kq * 4]) = v;
    }
    #pragma unroll
    for (int l = tid; l < 64 * 16; l += 256) {
        int i = l & 63, kq = l >> 6;
        float4 v = reinterpret_cast<const float4*>(Win + (size_t)(col0 + i) * OBS)[kq];
        Bs[kq * 4 + 0][i] = v.x;
        Bs[kq * 4 + 1][i] = v.y;
        Bs[kq * 4 + 2][i] = v.z;
        Bs[kq * 4 + 3][i] = v.w;
    }
    __syncthreads();

    const int tx = tid & 15, ty = tid >> 4;
    float acc[8][4];
    #pragma unroll
    for (int u = 0; u < 8; u++)
        #pragma unroll
        for (int c = 0; c < 4; c++) acc[u][c] = 0.f;

    #pragma unroll 8
    for (int k = 0; k < OBS; k++) {
        float4 b4 = *reinterpret_cast<const float4*>(&Bs[k][tx * 4]);
        #pragma unroll
        for (int u = 0; u < 8; u++) {
            float a = As[ty * 8 + u][k];
            acc[u][0] = __fmaf_rn(a, b4.x, acc[u][0]);
            acc[u][1] = __fmaf_rn(a, b4.y, acc[u][1]);
            acc[u][2] = __fmaf_rn(a, b4.z, acc[u][2]);
            acc[u][3] = __fmaf_rn(a, b4.w, acc[u][3]);
        }
    }
    #pragma unroll
    for (int u = 0; u < 8; u++) {
        size_t r = (size_t)(row0 + ty * 8 + u);
        float4 st = make_float4(acc[u][0], acc[u][1], acc[u][2], acc[u][3]);
        *reinterpret_cast<float4*>(&g_I[r * NN + col0 + tx * 4]) = st;
    }
}

// ---------- per-group barrier: 8 blocks, own 128B line, monotone target ----------
__device__ __forceinline__ void group_barrier(GroupBar* bar, unsigned target)
{
    __syncthreads();
    if (threadIdx.x == 0) {
        unsigned prev, one = 1u;
        asm volatile("atom.release.gpu.add.u32 %0, [%1], %2;"
                     : "=r"(prev) : "l"(&bar->count), "r"(one) : "memory");
        if (prev == target * NNT - 1u) {
            asm volatile("st.release.gpu.u32 [%0], %1;"
                         :: "l"(&bar->flag), "r"(target) : "memory");
        } else {
            unsigned f;
            do {
                asm volatile("ld.acquire.gpu.u32 %0, [%1];"
                             : "=r"(f) : "l"(&bar->flag) : "memory");
            } while (f < target);
        }
    }
    __syncthreads();
}

// bit j of x -> bit 2j (16-bit Morton spread)
__device__ __forceinline__ unsigned spread16(unsigned x)
{
    x = (x | (x << 8)) & 0x00FF00FFu;
    x = (x | (x << 4)) & 0x0F0F0F0Fu;
    x = (x | (x << 2)) & 0x33333333u;
    x = (x | (x << 1)) & 0x55555555u;
    return x;
}

// ---------- persistent LIF: W slice stationary in SMEM, per-group sync ----------
// block = (batch group bg) x (neuron tile nt); warp w -> row b0+w; lane owns
// ADJACENT neurons i0+2*lane, i0+2*lane+1 (one LDS.64 float2 per spike).
// State path bitwise-locked: ordered mask decode -> per-neuron strictly
// increasing-j sequential __fadd_rn chains; v' = fma(BETA,v,R)+I-s.
__global__ void __launch_bounds__(THREADS, 1) lif_kernel(float* __restrict__ out,
                                                         const float* __restrict__ Wout)
{
    extern __shared__ float smem[];
    float*          Ws     = smem;                               // [NN][NT], 128KB
    unsigned short* s_list = (unsigned short*)(smem + NN * NT);  // [BT][NN], 16KB

    const int blk  = blockIdx.x;
    const int bg   = blk >> 3;         // 0..15
    const int nt   = blk & 7;          // 0..7
    const int b0   = bg * BT;
    const int i0   = nt * NT;
    const int tid  = threadIdx.x;
    const int warp = tid >> 5, lane = tid & 31;
    const int b    = b0 + warp;        // this warp's batch row
    const bool finalizer = ((warp & 7) == nt);   // 2 warps/block finalize own rows
    GroupBar* bar = &g_bar[bg];

    // Load W slice (coalesced; layout Ws[j][il])
    {
        const int jl = tid >> 6, il = tid & 63;
        for (int j = jl; j < NN; j += 8)
            Ws[j * NT + il] = g_WT[j * NN + i0 + il];
    }
    __syncthreads();

    float wo0[AA], wo1[AA];
    #pragma unroll
    for (int a = 0; a < AA; a++) {
        wo0[a] = Wout[a * NN + i0 + 2 * lane];
        wo1[a] = Wout[a * NN + i0 + 2 * lane + 1];
    }

    const float*    Ibase = g_I + (size_t)b * TT * NN + i0 + 2 * lane;
    const float2*   wpl   = reinterpret_cast<const float2*>(Ws) + lane;
    unsigned short* lst   = s_list + warp * NN;

    float v0 = 0.f, v1 = 0.f;
    bool  sp0 = false, sp1 = false;
    float2 In = __ldg(reinterpret_cast<const float2*>(Ibase));   // I(0), 8B-aligned

    // masks(par0) zeroed by fused prep (kernel ordering); no initial barrier needed.
    for (int t = 0; t < TT; t++) {
        const int par = t & 1;

        // Prefetch I(t+1): off the critical path by a full step
        const float2 Ic = In;
        {
            int tn = (t + 1 < TT) ? t + 1 : t;
            In = __ldg(reinterpret_cast<const float2*>(Ibase + (size_t)tn * NN));
        }

        // Read my row's 16 mask words (one coalesced 64B L2 load) — issue early
        unsigned mw = (lane < 16) ? __ldcg(&g_mask[par][b][lane]) : 0u;

        // Finalize out(t-1) for my own row (output path: tolerance-checked)
        if (t > 0 && finalizer) {
            const float* P = &g_part[par ^ 1][b][0][0];   // 64 contiguous floats
            float s = __ldcg(P + lane) + __ldcg(P + 32 + lane);
            s += __shfl_xor_sync(0xffffffffu, s, 8);
            s += __shfl_xor_sync(0xffffffffu, s, 16);
            if (lane < AA)
                out[((size_t)b * TT + (t - 1)) * AA + lane] = tanhf(s);
        }

        // Decode masks to ordered spike list in smem (increasing j)
        int nsp = 0;
        #pragma unroll
        for (int w16 = 0; w16 < 16; w16++) {
            unsigned m = __shfl_sync(0xffffffffu, mw, w16);
            if ((m >> lane) & 1u)
                lst[nsp + __popc(m & ((1u << lane) - 1u))] = (unsigned short)(w16 * 32 + lane);
            nsp += __popc(m);
        }
        __syncwarp();

        // Sparse gather: one LDS.64 (both neurons) per spike, scalar rn adds.
        // Each neuron's accumulator chain is strictly increasing j.
        float R0 = 0.f, R1 = 0.f;
        int l = 0;
        for (; l + 4 <= nsp; l += 4) {
            ushort4 j4 = *reinterpret_cast<const ushort4*>(lst + l);
            float2 w0 = wpl[(int)j4.x * (NT / 2)];
            float2 w1 = wpl[(int)j4.y * (NT / 2)];
            float2 w2 = wpl[(int)j4.z * (NT / 2)];
            float2 w3 = wpl[(int)j4.w * (NT / 2)];
            R0 = __fadd_rn(R0, w0.x); R1 = __fadd_rn(R1, w0.y);
            R0 = __fadd_rn(R0, w1.x); R1 = __fadd_rn(R1, w1.y);
            R0 = __fadd_rn(R0, w2.x); R1 = __fadd_rn(R1, w2.y);
            R0 = __fadd_rn(R0, w3.x); R1 = __fadd_rn(R1, w3.y);
        }
        for (; l < nsp; l++) {
            float2 w = wpl[(int)lst[l] * (NT / 2)];
            R0 = __fadd_rn(R0, w.x); R1 = __fadd_rn(R1, w.y);
        }

        // v' = (fma(BETA,v,R) + I) - V_TH*s   (locked ordering)
        float acc0 = __fmaf_rn(BETA, v0, R0);
        acc0 = __fadd_rn(acc0, Ic.x);
        if (sp0) acc0 = __fadd_rn(acc0, -V_TH);
        v0 = acc0; sp0 = v0 > V_TH;

        float acc1 = __fmaf_rn(BETA, v1, R1);
        acc1 = __fadd_rn(acc1, Ic.y);
        if (sp1) acc1 = __fadd_rn(acc1, -V_TH);
        v1 = acc1; sp1 = v1 > V_TH;

        // Publish masks(t+1): de-interleave pair ballots into neuron-ordered words
        unsigned bal0 = __ballot_sync(0xffffffffu, sp0);   // neuron 2*lane
        unsigned bal1 = __ballot_sync(0xffffffffu, sp1);   // neuron 2*lane+1
        unsigned m0 = spread16(bal0 & 0xFFFFu) | (spread16(bal1 & 0xFFFFu) << 1);
        unsigned m1 = spread16(bal0 >> 16)     | (spread16(bal1 >> 16) << 1);

        float p[AA];
        #pragma unroll
        for (int a = 0; a < AA; a++) {
            p[a] = v0 * wo0[a] + v1 * wo1[a];
            #pragma unroll
            for (int off = 16; off > 0; off >>= 1)
                p[a] += __shfl_down_sync(0xffffffffu, p[a], off);
        }
        if (lane == 0) {
            g_mask[par ^ 1][b][nt * 2 + 0] = m0;
            g_mask[par ^ 1][b][nt * 2 + 1] = m1;
            #pragma unroll
            for (int a = 0; a < AA; a++) g_part[par][b][nt][a] = p[a];
        }

        group_barrier(bar, (unsigned)(t + 1));
    }

    // Finalize out(TT-1) (last barrier made partials(TT-1) visible group-wide)
    if (finalizer) {
        const float* P = &g_part[(TT - 1) & 1][b][0][0];
        float s = __ldcg(P + lane) + __ldcg(P + 32 + lane);
        s += __shfl_xor_sync(0xffffffffu, s, 8);
        s += __shfl_xor_sync(0xffffffffu, s, 16);
        if (lane < AA)
            out[((size_t)b * TT + (TT - 1)) * AA + lane] = tanhf(s);
    }
}

extern "C" void kernel_launch(void* const* d_in, const int* in_sizes, int n_in,
                              void* d_out, int out_size)
{
    const float* X    = (const float*)d_in[0];  // [B,T,OBS]
    const float* Wrec = (const float*)d_in[1];  // [N,N]
    const float* Win  = (const float*)d_in[2];  // [N,OBS]
    const float* Wout = (const float*)d_in[3];  // [A,N]
    float*       out  = (float*)d_out;          // [B,T,A]

    const int smem_bytes = NN * NT * 4 + BT * NN * 2;   // 128KB W + 16KB lists
    static bool attr_done = false;
    if (!attr_done) {
        cudaFuncSetAttribute(lif_kernel, cudaFuncAttributeMaxDynamicSharedMemorySize, smem_bytes);
        attr_done = true;
    }

    // 2 launches per call -> ncu -s 5 -c 1 lands on the lif kernel
    dim3 g((BB * TT) / 128, 9);   // y<8: gemm tiles; y==8: prep plane
    fused_prep_ingemm<<<g, 256>>>(X, Win, Wrec);
    lif_kernel<<<GRID, THREADS, smem_bytes>>>(out, Wout);
}